// round 6
// baseline (speedup 1.0000x reference)
#include <cuda_runtime.h>
#include <cuda_bf16.h>
#include <cstdint>
#include <cstddef>

// ---------------------------------------------------------------- constants
constexpr int B      = 4;
constexpr int NS     = 512;
constexpr int NQ     = 4096;
constexpr int D      = 128;
constexpr int NTOT   = NS + NQ;        // 4608
constexpr int NSPLIT = 8;              // query splits per support tile
constexpr int QSPL   = NQ / NSPLIT;    // 512 q per CTA
constexpr int SUBQ   = 64;             // q subtile
constexpr int NSUB   = QSPL / SUBQ;    // 8
constexpr int STILES = NS / 128;       // 4

constexpr int ROWB   = 272;            // smem row stride bytes (256 data + 16 pad)

// smem layout (dynamic)
constexpr int SM_S    = 0;                       // 128 x 272
constexpr int SM_Q0   = SM_S  + 128 * ROWB;      // 64 x 272
constexpr int SM_Q1   = SM_Q0 + 64 * ROWB;
constexpr int SM_QN0  = SM_Q1 + 64 * ROWB;       // 64 floats
constexpr int SM_QN1  = SM_QN0 + 256;
constexpr int SMEM_BYTES = SM_QN1 + 256;         // 70,656 B

// scratch (device globals: no allocation)
__device__ __nv_bfloat16 g_fbf16[(size_t)B * NTOT * D];                  // 4.7 MB
__device__ float g_qnorm[B * NQ];
__device__ float g_rpart[(size_t)B * STILES * NSPLIT * 128 * 128];       // 8.4 MB
__device__ float g_den[B * STILES * NSPLIT * 128];

// ---------------------------------------------------------------- helpers
__device__ __forceinline__ uint32_t smem_u32(const void* p) {
    uint32_t a;
    asm("{ .reg .u64 t; cvta.to.shared.u64 t, %1; cvt.u32.u64 %0, t; }"
        : "=r"(a) : "l"(p));
    return a;
}
__device__ __forceinline__ void cp16(uint32_t dst, const void* src) {
    asm volatile("cp.async.cg.shared.global [%0], [%1], 16;" :: "r"(dst), "l"(src));
}
#define CP_COMMIT() asm volatile("cp.async.commit_group;" ::: "memory")
#define CP_WAIT0()  asm volatile("cp.async.wait_group 0;" ::: "memory")

#define LDSM4(r0, r1, r2, r3, a) \
    asm volatile("ldmatrix.sync.aligned.m8n8.x4.shared.b16 {%0,%1,%2,%3}, [%4];" \
        : "=r"(r0), "=r"(r1), "=r"(r2), "=r"(r3) : "r"(a))
#define LDSM4T(r0, r1, r2, r3, a) \
    asm volatile("ldmatrix.sync.aligned.m8n8.x4.trans.shared.b16 {%0,%1,%2,%3}, [%4];" \
        : "=r"(r0), "=r"(r1), "=r"(r2), "=r"(r3) : "r"(a))

#define MMA16816(d, a, b0, b1) \
    asm volatile("mma.sync.aligned.m16n8k16.row.col.f32.bf16.bf16.f32 " \
        "{%0,%1,%2,%3}, {%4,%5,%6,%7}, {%8,%9}, {%0,%1,%2,%3};" \
        : "+f"((d)[0]), "+f"((d)[1]), "+f"((d)[2]), "+f"((d)[3]) \
        : "r"((a)[0]), "r"((a)[1]), "r"((a)[2]), "r"((a)[3]), "r"(b0), "r"(b1))

// ---------------------------------------------------------------- kernel 1: prep
// One warp per feature row: write bf16 copy; for query rows also ||q||^2.
// (fp32 query->out copy moved into attn_kernel, hidden under the MMA pipe.)
__global__ void __launch_bounds__(256) prep_kernel(const float* __restrict__ feat)
{
    int gwarp = (blockIdx.x * blockDim.x + threadIdx.x) >> 5;
    int lane  = threadIdx.x & 31;
    if (gwarp >= B * NTOT) return;
    int b = gwarp / NTOT;
    int n = gwarp - b * NTOT;

    size_t row = (size_t)b * NTOT + n;
    float4 v = ((const float4*)(feat + row * D))[lane];

    __nv_bfloat162 lo = __floats2bfloat162_rn(v.x, v.y);
    __nv_bfloat162 hi = __floats2bfloat162_rn(v.z, v.w);
    uint2 u;
    u.x = *(uint32_t*)&lo;
    u.y = *(uint32_t*)&hi;
    ((uint2*)(g_fbf16 + row * D))[lane] = u;

    if (n >= NS) {
        float ss = v.x*v.x + v.y*v.y + v.z*v.z + v.w*v.w;
        #pragma unroll
        for (int o = 16; o > 0; o >>= 1) ss += __shfl_xor_sync(0xffffffffu, ss, o);
        if (lane == 0) g_qnorm[b * NQ + (n - NS)] = ss;
    }
}

// ---------------------------------------------------------------- kernel 2: attention
__global__ void __launch_bounds__(256, 1) attn_kernel(const float* __restrict__ feat,
                                                      float* __restrict__ out)
{
    extern __shared__ char smem[];
    const int bid   = blockIdx.x;
    const int split = bid & 7;
    const int stile = (bid >> 3) & 3;
    const int b     = bid >> 5;
    const int tid   = threadIdx.x;
    const int wid   = tid >> 5;
    const int lane  = tid & 31;
    const uint32_t sb = smem_u32(smem);

    const char* Sg = (const char*)(g_fbf16 + ((size_t)b * NTOT + (size_t)stile * 128) * D);
    const char* Qg = (const char*)(g_fbf16 + ((size_t)b * NTOT + NS + (size_t)split * QSPL) * D);
    const float* qn_g = g_qnorm + b * NQ + split * QSPL;

    // fp32 query->out copy region: this CTA owns 128 unique rows
    // (rows [stile*128, stile*128+128) within its 512-row split).
    const size_t crow = (size_t)b * NTOT + NS + (size_t)split * QSPL + (size_t)stile * 128;
    const float4* csrc = (const float4*)(feat + crow * D);
    float4*       cdst = (float4*)(out  + crow * D);

    // ---- issue S tile (128 rows) + Q subtile 0 as one cp.async group
    #pragma unroll
    for (int i = 0; i < 8; ++i) {
        int c = tid + i * 256;                 // 0..2047
        int r = c >> 4, j = c & 15;
        cp16(sb + SM_S + r * ROWB + j * 16, Sg + r * 256 + j * 16);
    }
    #pragma unroll
    for (int i = 0; i < 4; ++i) {
        int c = tid + i * 256;                 // 0..1023
        int r = c >> 4, j = c & 15;
        cp16(sb + SM_Q0 + r * ROWB + j * 16, Qg + r * 256 + j * 16);
    }
    CP_COMMIT();
    if (tid < SUBQ) ((float*)(smem + SM_QN0))[tid] = qn_g[tid];

    CP_WAIT0();
    __syncthreads();

    // ---- load S A-fragments once: A[k][0..3], k = 8 steps of 16 d
    uint32_t A[8][4];
    {
        uint32_t arow = sb + SM_S + (16 * wid + (lane & 15)) * ROWB + ((lane >> 4) << 4);
        #pragma unroll
        for (int k = 0; k < 8; ++k)
            LDSM4(A[k][0], A[k][1], A[k][2], A[k][3], arow + k * 32);
    }

    float acc2[16][4];
    #pragma unroll
    for (int g = 0; g < 16; ++g)
        #pragma unroll
        for (int j = 0; j < 4; ++j) acc2[g][j] = 0.f;
    float den0 = 0.f, den1 = 0.f;

    for (int t = 0; t < NSUB; ++t) {
        const uint32_t qb  = sb + ((t & 1) ? SM_Q1 : SM_Q0);
        const float* qn_s  = (const float*)(smem + ((t & 1) ? SM_QN1 : SM_QN0));

        // fp32 copy loads for this iteration: 512 float4 / 256 threads = 2 each.
        // Issued here, consumed (stored) after GEMM2 -> latency hidden by MMAs.
        float4 cp0 = csrc[t * 512 + tid];
        float4 cp1 = csrc[t * 512 + tid + 256];

        // prefetch next subtile
        if (t + 1 < NSUB) {
            const char* src = Qg + (size_t)(t + 1) * SUBQ * 256;
            uint32_t dst = sb + (((t + 1) & 1) ? SM_Q1 : SM_Q0);
            #pragma unroll
            for (int i = 0; i < 4; ++i) {
                int c = tid + i * 256;
                int r = c >> 4, j = c & 15;
                cp16(dst + r * ROWB + j * 16, src + r * 256 + j * 16);
            }
            CP_COMMIT();
            if (tid < SUBQ)
                ((float*)(smem + (((t + 1) & 1) ? SM_QN1 : SM_QN0)))[tid] =
                    qn_g[(t + 1) * SUBQ + tid];
        }

        // ---- GEMM1: logits c1[8 n-tiles][4] = S . Q^T (K = 128 d)
        float c1[8][4];
        #pragma unroll
        for (int g = 0; g < 8; ++g)
            #pragma unroll
            for (int j = 0; j < 4; ++j) c1[g][j] = 0.f;

        {
            uint32_t baddr = qb + ((lane & 7) + ((lane >> 4) << 3)) * ROWB
                                + (((lane >> 3) & 1) << 4);
            #pragma unroll
            for (int k = 0; k < 8; ++k) {          // k16 over 128 d
                #pragma unroll
                for (int g = 0; g < 4; ++g) {      // n16 groups over 64 q
                    uint32_t b0, b1, b2, b3;
                    LDSM4(b0, b1, b2, b3, baddr + g * 16 * ROWB + k * 32);
                    MMA16816(c1[g * 2],     A[k], b0, b1);
                    MMA16816(c1[g * 2 + 1], A[k], b2, b3);
                }
            }
        }

        // ---- epilogue: w = exp(0.2*dot - 0.1*||q||^2), pack GEMM2 A frags
        uint32_t W[4][4];
        #pragma unroll
        for (int g = 0; g < 8; ++g) {
            int q0 = g * 8 + (lane & 3) * 2;
            float qa = qn_s[q0], qc = qn_s[q0 + 1];
            float w00 = __expf(0.2f * c1[g][0] - 0.1f * qa);
            float w01 = __expf(0.2f * c1[g][1] - 0.1f * qc);
            float w10 = __expf(0.2f * c1[g][2] - 0.1f * qa);
            float w11 = __expf(0.2f * c1[g][3] - 0.1f * qc);
            den0 += w00 + w01;
            den1 += w10 + w11;
            uint32_t p0, p1;
            asm("cvt.rn.satfinite.bf16x2.f32 %0, %1, %2;" : "=r"(p0) : "f"(w01), "f"(w00));
            asm("cvt.rn.satfinite.bf16x2.f32 %0, %1, %2;" : "=r"(p1) : "f"(w11), "f"(w10));
            int kk = g >> 1, h = g & 1;
            W[kk][h * 2 + 0] = p0;
            W[kk][h * 2 + 1] = p1;
        }

        // ---- GEMM2: acc2 += W . Q  (K = 64 q, N = 128 d), B = ldmatrix.trans
        {
            uint32_t baddr = qb + ((lane & 7) + (((lane >> 3) & 1) << 3)) * ROWB
                                + ((lane >> 4) << 4);
            #pragma unroll
            for (int kk = 0; kk < 4; ++kk) {       // k16 over 64 q
                #pragma unroll
                for (int g = 0; g < 8; ++g) {      // n16 over 128 d
                    uint32_t b0, b1, b2, b3;
                    LDSM4T(b0, b1, b2, b3, baddr + kk * 16 * ROWB + g * 32);
                    MMA16816(acc2[g * 2],     W[kk], b0, b1);
                    MMA16816(acc2[g * 2 + 1], W[kk], b2, b3);
                }
            }
        }

        // fp32 copy stores (loads have had ~2 GEMMs of latency cover)
        cdst[t * 512 + tid]       = cp0;
        cdst[t * 512 + tid + 256] = cp1;

        if (t + 1 < NSUB) {
            CP_WAIT0();
            __syncthreads();
        }
    }

    // ---- write partials
    const int rbase = ((b * STILES + stile) * NSPLIT + split) * 128;
    const int r0 = 16 * wid + (lane >> 2);
    float* rp0 = g_rpart + (size_t)(rbase + r0) * 128;
    float* rp1 = g_rpart + (size_t)(rbase + r0 + 8) * 128;
    #pragma unroll
    for (int g = 0; g < 16; ++g) {
        int dc = g * 8 + (lane & 3) * 2;
        *(float2*)(rp0 + dc) = make_float2(acc2[g][0], acc2[g][1]);
        *(float2*)(rp1 + dc) = make_float2(acc2[g][2], acc2[g][3]);
    }
    den0 += __shfl_xor_sync(0xffffffffu, den0, 1);
    den0 += __shfl_xor_sync(0xffffffffu, den0, 2);
    den1 += __shfl_xor_sync(0xffffffffu, den1, 1);
    den1 += __shfl_xor_sync(0xffffffffu, den1, 2);
    if ((lane & 3) == 0) {
        g_den[rbase + r0]     = den0;
        g_den[rbase + r0 + 8] = den1;
    }
}

// ---------------------------------------------------------------- kernel 3: combine
__global__ void __launch_bounds__(256) combine_kernel(const float* __restrict__ feat,
                                                      float* __restrict__ out)
{
    int gw   = (blockIdx.x * blockDim.x + threadIdx.x) >> 5;
    int lane = threadIdx.x & 31;
    if (gw >= B * NS) return;
    int b = gw >> 9;
    int s = gw & 511;
    int stile = s >> 7, r = s & 127;

    float4 acc = make_float4(0.f, 0.f, 0.f, 0.f);
    float den = 0.f;
    #pragma unroll
    for (int p = 0; p < NSPLIT; ++p) {
        size_t base = ((size_t)(b * STILES + stile) * NSPLIT + p) * 128 + r;
        float4 v = ((const float4*)(g_rpart + base * 128))[lane];
        acc.x += v.x; acc.y += v.y; acc.z += v.z; acc.w += v.w;
        den += g_den[base];
    }
    float inv = 0.9f / den;
    const float4 sv = ((const float4*)(feat + ((size_t)b * NTOT + s) * D))[lane];
    float4 o;
    o.x = 0.1f * sv.x + inv * acc.x;
    o.y = 0.1f * sv.y + inv * acc.y;
    o.z = 0.1f * sv.z + inv * acc.z;
    o.w = 0.1f * sv.w + inv * acc.w;
    ((float4*)(out + ((size_t)b * NTOT + s) * D))[lane] = o;
}

// ---------------------------------------------------------------- launch
extern "C" void kernel_launch(void* const* d_in, const int* in_sizes, int n_in,
                              void* d_out, int out_size)
{
    const float* feat = (const float*)d_in[0];   // (4, 4608, 128) fp32
    float* out = (float*)d_out;

    cudaFuncSetAttribute(attn_kernel, cudaFuncAttributeMaxDynamicSharedMemorySize,
                         SMEM_BYTES);

    prep_kernel<<<(B * NTOT * 32 + 255) / 256, 256>>>(feat);
    attn_kernel<<<B * STILES * NSPLIT, 256, SMEM_BYTES>>>(feat, out);
    combine_kernel<<<(B * NS * 32 + 255) / 256, 256>>>(feat, out);
}

// round 7
// speedup vs baseline: 1.0920x; 1.0920x over previous
#include <cuda_runtime.h>
#include <cuda_bf16.h>
#include <cstdint>
#include <cstddef>

// ---------------------------------------------------------------- constants
constexpr int B      = 4;
constexpr int NS     = 512;
constexpr int NQ     = 4096;
constexpr int D      = 128;
constexpr int NTOT   = NS + NQ;        // 4608
constexpr int NSPLIT = 8;              // query splits per support tile
constexpr int QSPL   = NQ / NSPLIT;    // 512 q per CTA
constexpr int SUBQ   = 64;             // q subtile
constexpr int NSUB   = QSPL / SUBQ;    // 8
constexpr int STILES = NS / 128;       // 4

constexpr int ROWB   = 272;            // smem row stride bytes (256 data + 16 pad)

// smem layout (dynamic)
constexpr int SM_S    = 0;                       // 128 x 272
constexpr int SM_Q0   = SM_S  + 128 * ROWB;      // 64 x 272
constexpr int SM_Q1   = SM_Q0 + 64 * ROWB;
constexpr int SM_QN0  = SM_Q1 + 64 * ROWB;       // 64 floats
constexpr int SM_QN1  = SM_QN0 + 256;
constexpr int SMEM_BYTES = SM_QN1 + 256;         // 70,656 B

// scratch (device globals: no allocation)
__device__ __nv_bfloat16 g_fbf16[(size_t)B * NTOT * D];                  // 4.7 MB
__device__ float g_qnorm[B * NQ];
__device__ float g_rpart[(size_t)B * STILES * NSPLIT * 128 * 128];       // 8.4 MB
__device__ float g_den[B * STILES * NSPLIT * 128];

// ---------------------------------------------------------------- helpers
__device__ __forceinline__ uint32_t smem_u32(const void* p) {
    uint32_t a;
    asm("{ .reg .u64 t; cvta.to.shared.u64 t, %1; cvt.u32.u64 %0, t; }"
        : "=r"(a) : "l"(p));
    return a;
}
__device__ __forceinline__ void cp16(uint32_t dst, const void* src) {
    asm volatile("cp.async.cg.shared.global [%0], [%1], 16;" :: "r"(dst), "l"(src));
}
#define CP_COMMIT() asm volatile("cp.async.commit_group;" ::: "memory")
#define CP_WAIT0()  asm volatile("cp.async.wait_group 0;" ::: "memory")

#define LDSM4(r0, r1, r2, r3, a) \
    asm volatile("ldmatrix.sync.aligned.m8n8.x4.shared.b16 {%0,%1,%2,%3}, [%4];" \
        : "=r"(r0), "=r"(r1), "=r"(r2), "=r"(r3) : "r"(a))
#define LDSM4T(r0, r1, r2, r3, a) \
    asm volatile("ldmatrix.sync.aligned.m8n8.x4.trans.shared.b16 {%0,%1,%2,%3}, [%4];" \
        : "=r"(r0), "=r"(r1), "=r"(r2), "=r"(r3) : "r"(a))

#define MMA16816(d, a, b0, b1) \
    asm volatile("mma.sync.aligned.m16n8k16.row.col.f32.bf16.bf16.f32 " \
        "{%0,%1,%2,%3}, {%4,%5,%6,%7}, {%8,%9}, {%0,%1,%2,%3};" \
        : "+f"((d)[0]), "+f"((d)[1]), "+f"((d)[2]), "+f"((d)[3]) \
        : "r"((a)[0]), "r"((a)[1]), "r"((a)[2]), "r"((a)[3]), "r"(b0), "r"(b1))

// ---------------------------------------------------------------- kernel 1: prep
// 4 rows per warp, 4 independent LDG.128 per thread (MLP=4, single wave).
// Writes bf16 copy; for query rows also fp32 copy to out and ||q||^2.
// Row groups of 4 never straddle the support/query or batch boundary
// (512 and 4608 are multiples of 4).
__global__ void __launch_bounds__(256) prep_kernel(const float* __restrict__ feat,
                                                   float* __restrict__ out)
{
    int gwarp = (blockIdx.x * blockDim.x + threadIdx.x) >> 5;
    int lane  = threadIdx.x & 31;
    if (gwarp >= B * NTOT / 4) return;
    int base = gwarp * 4;                       // first global row of group
    int b = base / NTOT;
    int n = base - b * NTOT;

    const float4* src = (const float4*)(feat + (size_t)base * D);
    float4 v0 = src[lane];
    float4 v1 = src[lane + 32];
    float4 v2 = src[lane + 64];
    float4 v3 = src[lane + 96];

    uint2* bdst = (uint2*)(g_fbf16 + (size_t)base * D);
    #define PACK_STORE(v, ofs) do {                                   \
        __nv_bfloat162 lo = __floats2bfloat162_rn((v).x, (v).y);      \
        __nv_bfloat162 hi = __floats2bfloat162_rn((v).z, (v).w);      \
        uint2 u; u.x = *(uint32_t*)&lo; u.y = *(uint32_t*)&hi;        \
        bdst[lane + (ofs)] = u;                                       \
    } while (0)
    PACK_STORE(v0, 0);
    PACK_STORE(v1, 32);
    PACK_STORE(v2, 64);
    PACK_STORE(v3, 96);
    #undef PACK_STORE

    if (n >= NS) {
        float4* cdst = (float4*)(out + (size_t)base * D);
        cdst[lane]      = v0;
        cdst[lane + 32] = v1;
        cdst[lane + 64] = v2;
        cdst[lane + 96] = v3;

        float s0 = v0.x*v0.x + v0.y*v0.y + v0.z*v0.z + v0.w*v0.w;
        float s1 = v1.x*v1.x + v1.y*v1.y + v1.z*v1.z + v1.w*v1.w;
        float s2 = v2.x*v2.x + v2.y*v2.y + v2.z*v2.z + v2.w*v2.w;
        float s3 = v3.x*v3.x + v3.y*v3.y + v3.z*v3.z + v3.w*v3.w;
        #pragma unroll
        for (int o = 16; o > 0; o >>= 1) {
            s0 += __shfl_xor_sync(0xffffffffu, s0, o);
            s1 += __shfl_xor_sync(0xffffffffu, s1, o);
            s2 += __shfl_xor_sync(0xffffffffu, s2, o);
            s3 += __shfl_xor_sync(0xffffffffu, s3, o);
        }
        if (lane == 0) {
            float* qn = g_qnorm + b * NQ + (n - NS);
            qn[0] = s0; qn[1] = s1; qn[2] = s2; qn[3] = s3;
        }
    }
}

// ---------------------------------------------------------------- kernel 2: attention
__global__ void __launch_bounds__(256, 1) attn_kernel()
{
    extern __shared__ char smem[];
    const int bid   = blockIdx.x;
    const int split = bid & 7;
    const int stile = (bid >> 3) & 3;
    const int b     = bid >> 5;
    const int tid   = threadIdx.x;
    const int wid   = tid >> 5;
    const int lane  = tid & 31;
    const uint32_t sb = smem_u32(smem);

    const char* Sg = (const char*)(g_fbf16 + ((size_t)b * NTOT + (size_t)stile * 128) * D);
    const char* Qg = (const char*)(g_fbf16 + ((size_t)b * NTOT + NS + (size_t)split * QSPL) * D);
    const float* qn_g = g_qnorm + b * NQ + split * QSPL;

    // ---- issue S tile (128 rows) + Q subtile 0 as one cp.async group
    #pragma unroll
    for (int i = 0; i < 8; ++i) {
        int c = tid + i * 256;                 // 0..2047
        int r = c >> 4, j = c & 15;
        cp16(sb + SM_S + r * ROWB + j * 16, Sg + r * 256 + j * 16);
    }
    #pragma unroll
    for (int i = 0; i < 4; ++i) {
        int c = tid + i * 256;                 // 0..1023
        int r = c >> 4, j = c & 15;
        cp16(sb + SM_Q0 + r * ROWB + j * 16, Qg + r * 256 + j * 16);
    }
    CP_COMMIT();
    if (tid < SUBQ) ((float*)(smem + SM_QN0))[tid] = qn_g[tid];

    CP_WAIT0();
    __syncthreads();

    // ---- load S A-fragments once: A[k][0..3], k = 8 steps of 16 d
    uint32_t A[8][4];
    {
        uint32_t arow = sb + SM_S + (16 * wid + (lane & 15)) * ROWB + ((lane >> 4) << 4);
        #pragma unroll
        for (int k = 0; k < 8; ++k)
            LDSM4(A[k][0], A[k][1], A[k][2], A[k][3], arow + k * 32);
    }

    float acc2[16][4];
    #pragma unroll
    for (int g = 0; g < 16; ++g)
        #pragma unroll
        for (int j = 0; j < 4; ++j) acc2[g][j] = 0.f;
    float den0 = 0.f, den1 = 0.f;

    for (int t = 0; t < NSUB; ++t) {
        const uint32_t qb  = sb + ((t & 1) ? SM_Q1 : SM_Q0);
        const float* qn_s  = (const float*)(smem + ((t & 1) ? SM_QN1 : SM_QN0));

        // prefetch next subtile
        if (t + 1 < NSUB) {
            const char* src = Qg + (size_t)(t + 1) * SUBQ * 256;
            uint32_t dst = sb + (((t + 1) & 1) ? SM_Q1 : SM_Q0);
            #pragma unroll
            for (int i = 0; i < 4; ++i) {
                int c = tid + i * 256;
                int r = c >> 4, j = c & 15;
                cp16(dst + r * ROWB + j * 16, src + r * 256 + j * 16);
            }
            CP_COMMIT();
            if (tid < SUBQ)
                ((float*)(smem + (((t + 1) & 1) ? SM_QN1 : SM_QN0)))[tid] =
                    qn_g[(t + 1) * SUBQ + tid];
        }

        // ---- GEMM1: logits c1[8 n-tiles][4] = S . Q^T (K = 128 d)
        float c1[8][4];
        #pragma unroll
        for (int g = 0; g < 8; ++g)
            #pragma unroll
            for (int j = 0; j < 4; ++j) c1[g][j] = 0.f;

        {
            uint32_t baddr = qb + ((lane & 7) + ((lane >> 4) << 3)) * ROWB
                                + (((lane >> 3) & 1) << 4);
            #pragma unroll
            for (int k = 0; k < 8; ++k) {          // k16 over 128 d
                #pragma unroll
                for (int g = 0; g < 4; ++g) {      // n16 groups over 64 q
                    uint32_t b0, b1, b2, b3;
                    LDSM4(b0, b1, b2, b3, baddr + g * 16 * ROWB + k * 32);
                    MMA16816(c1[g * 2],     A[k], b0, b1);
                    MMA16816(c1[g * 2 + 1], A[k], b2, b3);
                }
            }
        }

        // ---- epilogue: w = exp(0.2*dot - 0.1*||q||^2), pack GEMM2 A frags
        uint32_t W[4][4];
        #pragma unroll
        for (int g = 0; g < 8; ++g) {
            int q0 = g * 8 + (lane & 3) * 2;
            float qa = qn_s[q0], qc = qn_s[q0 + 1];
            float w00 = __expf(0.2f * c1[g][0] - 0.1f * qa);
            float w01 = __expf(0.2f * c1[g][1] - 0.1f * qc);
            float w10 = __expf(0.2f * c1[g][2] - 0.1f * qa);
            float w11 = __expf(0.2f * c1[g][3] - 0.1f * qc);
            den0 += w00 + w01;
            den1 += w10 + w11;
            uint32_t p0, p1;
            asm("cvt.rn.satfinite.bf16x2.f32 %0, %1, %2;" : "=r"(p0) : "f"(w01), "f"(w00));
            asm("cvt.rn.satfinite.bf16x2.f32 %0, %1, %2;" : "=r"(p1) : "f"(w11), "f"(w10));
            int kk = g >> 1, h = g & 1;
            W[kk][h * 2 + 0] = p0;
            W[kk][h * 2 + 1] = p1;
        }

        // ---- GEMM2: acc2 += W . Q  (K = 64 q, N = 128 d), B = ldmatrix.trans
        {
            uint32_t baddr = qb + ((lane & 7) + (((lane >> 3) & 1) << 3)) * ROWB
                                + ((lane >> 4) << 4);
            #pragma unroll
            for (int kk = 0; kk < 4; ++kk) {       // k16 over 64 q
                #pragma unroll
                for (int g = 0; g < 8; ++g) {      // n16 over 128 d
                    uint32_t b0, b1, b2, b3;
                    LDSM4T(b0, b1, b2, b3, baddr + kk * 16 * ROWB + g * 32);
                    MMA16816(acc2[g * 2],     W[kk], b0, b1);
                    MMA16816(acc2[g * 2 + 1], W[kk], b2, b3);
                }
            }
        }

        if (t + 1 < NSUB) {
            CP_WAIT0();
            __syncthreads();
        }
    }

    // ---- write partials
    const int rbase = ((b * STILES + stile) * NSPLIT + split) * 128;
    const int r0 = 16 * wid + (lane >> 2);
    float* rp0 = g_rpart + (size_t)(rbase + r0) * 128;
    float* rp1 = g_rpart + (size_t)(rbase + r0 + 8) * 128;
    #pragma unroll
    for (int g = 0; g < 16; ++g) {
        int dc = g * 8 + (lane & 3) * 2;
        *(float2*)(rp0 + dc) = make_float2(acc2[g][0], acc2[g][1]);
        *(float2*)(rp1 + dc) = make_float2(acc2[g][2], acc2[g][3]);
    }
    den0 += __shfl_xor_sync(0xffffffffu, den0, 1);
    den0 += __shfl_xor_sync(0xffffffffu, den0, 2);
    den1 += __shfl_xor_sync(0xffffffffu, den1, 1);
    den1 += __shfl_xor_sync(0xffffffffu, den1, 2);
    if ((lane & 3) == 0) {
        g_den[rbase + r0]     = den0;
        g_den[rbase + r0 + 8] = den1;
    }
}

// ---------------------------------------------------------------- kernel 3: combine
__global__ void __launch_bounds__(256) combine_kernel(const float* __restrict__ feat,
                                                      float* __restrict__ out)
{
    int gw   = (blockIdx.x * blockDim.x + threadIdx.x) >> 5;
    int lane = threadIdx.x & 31;
    if (gw >= B * NS) return;
    int b = gw >> 9;
    int s = gw & 511;
    int stile = s >> 7, r = s & 127;

    float4 acc = make_float4(0.f, 0.f, 0.f, 0.f);
    float den = 0.f;
    #pragma unroll
    for (int p = 0; p < NSPLIT; ++p) {
        size_t base = ((size_t)(b * STILES + stile) * NSPLIT + p) * 128 + r;
        float4 v = ((const float4*)(g_rpart + base * 128))[lane];
        acc.x += v.x; acc.y += v.y; acc.z += v.z; acc.w += v.w;
        den += g_den[base];
    }
    float inv = 0.9f / den;
    const float4 sv = ((const float4*)(feat + ((size_t)b * NTOT + s) * D))[lane];
    float4 o;
    o.x = 0.1f * sv.x + inv * acc.x;
    o.y = 0.1f * sv.y + inv * acc.y;
    o.z = 0.1f * sv.z + inv * acc.z;
    o.w = 0.1f * sv.w + inv * acc.w;
    ((float4*)(out + ((size_t)b * NTOT + s) * D))[lane] = o;
}

// ---------------------------------------------------------------- launch
extern "C" void kernel_launch(void* const* d_in, const int* in_sizes, int n_in,
                              void* d_out, int out_size)
{
    const float* feat = (const float*)d_in[0];   // (4, 4608, 128) fp32
    float* out = (float*)d_out;

    cudaFuncSetAttribute(attn_kernel, cudaFuncAttributeMaxDynamicSharedMemorySize,
                         SMEM_BYTES);

    prep_kernel<<<(B * NTOT / 4 * 32 + 255) / 256, 256>>>(feat, out);
    attn_kernel<<<B * STILES * NSPLIT, 256, SMEM_BYTES>>>();
    combine_kernel<<<(B * NS * 32 + 255) / 256, 256>>>(feat, out);
}